// round 12
// baseline (speedup 1.0000x reference)
#include <cuda_runtime.h>

#define NMAX 100000
#define EMAX 1600000
#define TOTEMAX (NMAX + EMAX)

// ---------------- scratch (static device globals; no allocation) ----------------
__device__ float g_hfeat[(size_t)NMAX * 128];          // per-layer linear features
__device__ float g_agg[(size_t)NMAX * 128];            // aggregated output (post-ELU)
__device__ float g_alpha[(size_t)TOTEMAX * 8];         // per-edge exp(e - m) per head
__device__ float g_as[(size_t)NMAX * 8];
__device__ float g_ad[(size_t)NMAX * 8];
__device__ float g_feat3[(size_t)NMAX * 6];
__device__ float g_as3[NMAX];
__device__ float g_ad3[NMAX];
__device__ int   g_cnt[NMAX];
__device__ int   g_rowstart[NMAX + 1];
__device__ int   g_fill[NMAX];
__device__ int   g_adj[TOTEMAX];
__device__ int   g_bsum[256];
__device__ int   g_boff[256];

// ---------------- CSR build ----------------
__global__ void k_count_init(int n) {
    int i = blockIdx.x * blockDim.x + threadIdx.x;
    if (i < n) g_cnt[i] = 1;  // self-loop
}

// edge_index is int32 (JAX x64 is disabled; jnp.int64 silently demotes to int32)
__global__ void k_count_edges(const int* __restrict__ ei, int E, int n) {
    int e = blockIdx.x * blockDim.x + threadIdx.x;
    if (e < E) {
        int d = ei[(size_t)E + e];
        if (d >= 0 && d < n) atomicAdd(&g_cnt[d], 1);
    }
}

// block of 256 threads scans 1024 items
__global__ void k_scan_local(int n) {
    __shared__ int sh[256];
    int t = threadIdx.x;
    int base = blockIdx.x * 1024 + t * 4;
    int v0 = (base + 0 < n) ? g_cnt[base + 0] : 0;
    int v1 = (base + 1 < n) ? g_cnt[base + 1] : 0;
    int v2 = (base + 2 < n) ? g_cnt[base + 2] : 0;
    int v3 = (base + 3 < n) ? g_cnt[base + 3] : 0;
    int s = v0 + v1 + v2 + v3;
    sh[t] = s;
    __syncthreads();
    for (int o = 1; o < 256; o <<= 1) {
        int x = (t >= o) ? sh[t - o] : 0;
        __syncthreads();
        sh[t] += x;
        __syncthreads();
    }
    int run = sh[t] - s;  // exclusive prefix of this thread within block
    if (base + 0 < n) g_rowstart[base + 0] = run; run += v0;
    if (base + 1 < n) g_rowstart[base + 1] = run; run += v1;
    if (base + 2 < n) g_rowstart[base + 2] = run; run += v2;
    if (base + 3 < n) g_rowstart[base + 3] = run;
    if (t == 255) g_bsum[blockIdx.x] = sh[255];
}

__global__ void k_scan_tops(int nb) {
    if (threadIdx.x == 0 && blockIdx.x == 0) {
        int run = 0;
        for (int b = 0; b < nb; b++) { g_boff[b] = run; run += g_bsum[b]; }
    }
}

__global__ void k_scan_apply(int n) {
    int i = blockIdx.x * blockDim.x + threadIdx.x;
    if (i < n) {
        int rs = g_rowstart[i] + g_boff[i >> 10];
        g_rowstart[i] = rs;
        g_fill[i] = rs;
        if (i == n - 1) g_rowstart[n] = rs + g_cnt[i];
    }
}

__global__ void k_fill(const int* __restrict__ ei, int E, int n) {
    int idx = blockIdx.x * blockDim.x + threadIdx.x;
    if (idx < E) {
        int s = ei[idx];
        int d = ei[(size_t)E + idx];
        if (d >= 0 && d < n && s >= 0 && s < n) {
            int pos = atomicAdd(&g_fill[d], 1);
            if (pos >= 0 && pos < TOTEMAX) g_adj[pos] = s;
        }
    } else if (idx < E + n) {
        int v = idx - E;
        int pos = atomicAdd(&g_fill[v], 1);
        if (pos >= 0 && pos < TOTEMAX) g_adj[pos] = v;
    }
}

// ---------------- SGEMM: C[nrows,K] = A[nrows,M] @ B[M,K]  (128x128 tile, 8x8/thread) ----------------
__global__ __launch_bounds__(256) void k_gemm(const float* __restrict__ A,
                                              const float* __restrict__ B,
                                              float* __restrict__ C,
                                              int nrows, int M, int K) {
    __shared__ float As[8][128];
    __shared__ float Bs[8][128];
    int tid = threadIdx.x;
    int rowBase = blockIdx.x * 128;
    int colBase = blockIdx.y * 128;
    int aRow = tid >> 1;
    int aCol = (tid & 1) * 4;
    int bRow = tid >> 5;
    int bCol = (tid & 31) * 4;
    int ty = tid >> 4, tx = tid & 15;

    float acc[8][8];
#pragma unroll
    for (int i = 0; i < 8; i++)
#pragma unroll
        for (int j = 0; j < 8; j++) acc[i][j] = 0.0f;

    for (int k0 = 0; k0 < M; k0 += 8) {
        float4 av = make_float4(0.f, 0.f, 0.f, 0.f);
        int r = rowBase + aRow;
        if (r < nrows) av = *reinterpret_cast<const float4*>(A + (size_t)r * M + k0 + aCol);
        As[aCol + 0][aRow] = av.x;
        As[aCol + 1][aRow] = av.y;
        As[aCol + 2][aRow] = av.z;
        As[aCol + 3][aRow] = av.w;
        float4 bv = *reinterpret_cast<const float4*>(B + (size_t)(k0 + bRow) * K + colBase + bCol);
        *reinterpret_cast<float4*>(&Bs[bRow][bCol]) = bv;
        __syncthreads();
#pragma unroll
        for (int kk = 0; kk < 8; kk++) {
            float ar[8], br[8];
#pragma unroll
            for (int i = 0; i < 8; i++) ar[i] = As[kk][ty * 8 + i];
#pragma unroll
            for (int j = 0; j < 8; j++) br[j] = Bs[kk][tx * 8 + j];
#pragma unroll
            for (int i = 0; i < 8; i++)
#pragma unroll
                for (int j = 0; j < 8; j++) acc[i][j] += ar[i] * br[j];
        }
        __syncthreads();
    }
#pragma unroll
    for (int i = 0; i < 8; i++) {
        int r = rowBase + ty * 8 + i;
        if (r < nrows) {
            float4 v0 = make_float4(acc[i][0], acc[i][1], acc[i][2], acc[i][3]);
            float4 v1 = make_float4(acc[i][4], acc[i][5], acc[i][6], acc[i][7]);
            *reinterpret_cast<float4*>(C + (size_t)r * K + colBase + tx * 8) = v0;
            *reinterpret_cast<float4*>(C + (size_t)r * K + colBase + tx * 8 + 4) = v1;
        }
    }
}

// ---------------- attention coefficients a_s, a_d  (8 heads x 16 dims) ----------------
__global__ void k_coef(const float* __restrict__ h, const float* __restrict__ attS,
                       const float* __restrict__ attD, int n) {
    int idx = blockIdx.x * blockDim.x + threadIdx.x;
    if (idx >= n * 8) return;
    int node = idx >> 3, hh = idx & 7;
    const float* hp = h + (size_t)node * 128 + hh * 16;
    const float* sp = attS + hh * 16;
    const float* dp = attD + hh * 16;
    float a = 0.f, b = 0.f;
#pragma unroll
    for (int j = 0; j < 16; j++) {
        float v = hp[j];
        a += v * sp[j];
        b += v * dp[j];
    }
    g_as[idx] = a;
    g_ad[idx] = b;
}

// ---------------- per-node softmax + aggregation (layers 1/2, H=8, D=16) ----------------
__global__ __launch_bounds__(256) void k_attn(const float* __restrict__ hfeat,
                                              float* __restrict__ outbuf,
                                              const float* __restrict__ bias,
                                              int n, int applyElu) {
    int w = (int)((blockIdx.x * blockDim.x + threadIdx.x) >> 5);
    int lane = threadIdx.x & 31;
    if (w >= n) return;
    int r0 = g_rowstart[w];
    int r1 = g_rowstart[w + 1];

    float ad[8];
    {
        const float4* adp = reinterpret_cast<const float4*>(g_ad + (size_t)w * 8);
        float4 d0 = adp[0], d1 = adp[1];
        ad[0] = d0.x; ad[1] = d0.y; ad[2] = d0.z; ad[3] = d0.w;
        ad[4] = d1.x; ad[5] = d1.y; ad[6] = d1.z; ad[7] = d1.w;
    }

    // pass 1: per-head max
    float mx[8];
#pragma unroll
    for (int h = 0; h < 8; h++) mx[h] = -3.4e38f;
    for (int i = r0 + lane; i < r1; i += 32) {
        int s = g_adj[i];
        const float4* ap = reinterpret_cast<const float4*>(g_as + (size_t)s * 8);
        float4 A0 = ap[0], A1 = ap[1];
        float ev[8] = {A0.x + ad[0], A0.y + ad[1], A0.z + ad[2], A0.w + ad[3],
                       A1.x + ad[4], A1.y + ad[5], A1.z + ad[6], A1.w + ad[7]};
#pragma unroll
        for (int h = 0; h < 8; h++) {
            float e = ev[h];
            e = (e > 0.f) ? e : 0.2f * e;
            mx[h] = fmaxf(mx[h], e);
        }
    }
#pragma unroll
    for (int h = 0; h < 8; h++)
        for (int o = 16; o > 0; o >>= 1)
            mx[h] = fmaxf(mx[h], __shfl_xor_sync(0xffffffffu, mx[h], o));

    // pass 2: exp(e - m), store, accumulate denominator
    float den[8];
#pragma unroll
    for (int h = 0; h < 8; h++) den[h] = 0.f;
    for (int i = r0 + lane; i < r1; i += 32) {
        int s = g_adj[i];
        const float4* ap = reinterpret_cast<const float4*>(g_as + (size_t)s * 8);
        float4 A0 = ap[0], A1 = ap[1];
        float ev[8] = {A0.x + ad[0], A0.y + ad[1], A0.z + ad[2], A0.w + ad[3],
                       A1.x + ad[4], A1.y + ad[5], A1.z + ad[6], A1.w + ad[7]};
        float ex[8];
#pragma unroll
        for (int h = 0; h < 8; h++) {
            float e = ev[h];
            e = (e > 0.f) ? e : 0.2f * e;
            float xx = __expf(e - mx[h]);
            ex[h] = xx;
            den[h] += xx;
        }
        float4* alp = reinterpret_cast<float4*>(g_alpha + (size_t)i * 8);
        alp[0] = make_float4(ex[0], ex[1], ex[2], ex[3]);
        alp[1] = make_float4(ex[4], ex[5], ex[6], ex[7]);
    }
    float inv[8];
#pragma unroll
    for (int h = 0; h < 8; h++) {
        for (int o = 16; o > 0; o >>= 1)
            den[h] += __shfl_xor_sync(0xffffffffu, den[h], o);
        inv[h] = 1.0f / (den[h] + 1e-16f);
    }

    // pass 3: feature aggregation. lane owns columns [lane*4, lane*4+4), head = lane/4
    int cb = lane * 4;
    int hh = lane >> 2;
    float invm = inv[0];
#pragma unroll
    for (int h = 1; h < 8; h++)
        if (hh == h) invm = inv[h];

    float4 acc = make_float4(0.f, 0.f, 0.f, 0.f);
    for (int i = r0; i < r1; i++) {
        int s = g_adj[i];
        float al = g_alpha[(size_t)i * 8 + hh] * invm;
        float4 hv = *reinterpret_cast<const float4*>(hfeat + (size_t)s * 128 + cb);
        acc.x += hv.x * al;
        acc.y += hv.y * al;
        acc.z += hv.z * al;
        acc.w += hv.w * al;
    }
    float4 bo = *reinterpret_cast<const float4*>(bias + cb);
    acc.x += bo.x; acc.y += bo.y; acc.z += bo.z; acc.w += bo.w;
    if (applyElu) {
        acc.x = (acc.x > 0.f) ? acc.x : (__expf(acc.x) - 1.f);
        acc.y = (acc.y > 0.f) ? acc.y : (__expf(acc.y) - 1.f);
        acc.z = (acc.z > 0.f) ? acc.z : (__expf(acc.z) - 1.f);
        acc.w = (acc.w > 0.f) ? acc.w : (__expf(acc.w) - 1.f);
    }
    *reinterpret_cast<float4*>(outbuf + (size_t)w * 128 + cb) = acc;
}

// ---------------- layer 3: tiny GEMM (128->6) + attention coefficients fused ----------------
__global__ void k_layer3(const float* __restrict__ h, const float* __restrict__ W3,
                         const float* __restrict__ aS, const float* __restrict__ aD, int n) {
    int v = blockIdx.x * blockDim.x + threadIdx.x;
    if (v >= n) return;
    float acc[6] = {0.f, 0.f, 0.f, 0.f, 0.f, 0.f};
    const float* hp = h + (size_t)v * 128;
    for (int m = 0; m < 128; m++) {
        float hv = hp[m];
#pragma unroll
        for (int c = 0; c < 6; c++) acc[c] += hv * W3[m * 6 + c];
    }
    float a = 0.f, b = 0.f;
#pragma unroll
    for (int c = 0; c < 6; c++) {
        g_feat3[(size_t)v * 6 + c] = acc[c];
        a += acc[c] * aS[c];
        b += acc[c] * aD[c];
    }
    g_as3[v] = a;
    g_ad3[v] = b;
}

// ---------------- layer 3 attention (H=1, C=6) -> final output ----------------
__global__ __launch_bounds__(256) void k_attn3(const float* __restrict__ b3,
                                               float* __restrict__ out, int n) {
    int w = (int)((blockIdx.x * blockDim.x + threadIdx.x) >> 5);
    int lane = threadIdx.x & 31;
    if (w >= n) return;
    int r0 = g_rowstart[w];
    int r1 = g_rowstart[w + 1];
    float adv = g_ad3[w];

    float mx = -3.4e38f;
    for (int i = r0 + lane; i < r1; i += 32) {
        int s = g_adj[i];
        float e = g_as3[s] + adv;
        e = (e > 0.f) ? e : 0.2f * e;
        mx = fmaxf(mx, e);
    }
    for (int o = 16; o > 0; o >>= 1)
        mx = fmaxf(mx, __shfl_xor_sync(0xffffffffu, mx, o));

    float den = 0.f;
    for (int i = r0 + lane; i < r1; i += 32) {
        int s = g_adj[i];
        float e = g_as3[s] + adv;
        e = (e > 0.f) ? e : 0.2f * e;
        den += __expf(e - mx);
    }
    for (int o = 16; o > 0; o >>= 1)
        den += __shfl_xor_sync(0xffffffffu, den, o);
    float inv = 1.0f / (den + 1e-16f);

    float acc[6] = {0.f, 0.f, 0.f, 0.f, 0.f, 0.f};
    for (int i = r0 + lane; i < r1; i += 32) {
        int s = g_adj[i];
        float e = g_as3[s] + adv;
        e = (e > 0.f) ? e : 0.2f * e;
        float al = __expf(e - mx) * inv;
#pragma unroll
        for (int c = 0; c < 6; c++) acc[c] += g_feat3[(size_t)s * 6 + c] * al;
    }
#pragma unroll
    for (int c = 0; c < 6; c++)
        for (int o = 16; o > 0; o >>= 1)
            acc[c] += __shfl_xor_sync(0xffffffffu, acc[c], o);

    if (lane < 6) {
        float v = acc[0];
#pragma unroll
        for (int c = 1; c < 6; c++)
            if (lane == c) v = acc[c];
        out[(size_t)w * 6 + lane] = v + b3[lane];
    }
}

// ---------------- launch ----------------
extern "C" void kernel_launch(void* const* d_in, const int* in_sizes, int n_in,
                              void* d_out, int out_size) {
    const float* x    = (const float*)d_in[0];
    const int*   ei   = (const int*)d_in[1];   // int32! (JAX x64 disabled demotes int64)
    const float* W1   = (const float*)d_in[2];
    const float* b1   = (const float*)d_in[3];
    const float* aS1  = (const float*)d_in[4];
    const float* aD1  = (const float*)d_in[5];
    const float* W2   = (const float*)d_in[6];
    const float* b2   = (const float*)d_in[7];
    const float* aS2  = (const float*)d_in[8];
    const float* aD2  = (const float*)d_in[9];
    const float* W3   = (const float*)d_in[10];
    const float* b3   = (const float*)d_in[11];
    const float* aS3  = (const float*)d_in[12];
    const float* aD3  = (const float*)d_in[13];
    float* out = (float*)d_out;

    int N = in_sizes[0] / 256;
    int E = in_sizes[1] / 2;
    int TE = E + N;

    float *p_hfeat, *p_agg;
    cudaGetSymbolAddress((void**)&p_hfeat, g_hfeat);
    cudaGetSymbolAddress((void**)&p_agg, g_agg);

    // ---- CSR build (by destination) ----
    k_count_init<<<(N + 255) / 256, 256>>>(N);
    k_count_edges<<<(E + 255) / 256, 256>>>(ei, E, N);
    int nb = (N + 1023) / 1024;
    k_scan_local<<<nb, 256>>>(N);
    k_scan_tops<<<1, 32>>>(nb);
    k_scan_apply<<<(N + 255) / 256, 256>>>(N);
    k_fill<<<(TE + 255) / 256, 256>>>(ei, E, N);

    dim3 ggrid((N + 127) / 128, 1);
    int attnBlocks = (N + 7) / 8;

    // ---- layer 1 ----
    k_gemm<<<ggrid, 256>>>(x, W1, p_hfeat, N, 256, 128);
    k_coef<<<(N * 8 + 255) / 256, 256>>>(p_hfeat, aS1, aD1, N);
    k_attn<<<attnBlocks, 256>>>(p_hfeat, p_agg, b1, N, 1);

    // ---- layer 2 ----
    k_gemm<<<ggrid, 256>>>(p_agg, W2, p_hfeat, N, 128, 128);
    k_coef<<<(N * 8 + 255) / 256, 256>>>(p_hfeat, aS2, aD2, N);
    k_attn<<<attnBlocks, 256>>>(p_hfeat, p_agg, b2, N, 1);

    // ---- layer 3 ----
    k_layer3<<<(N + 127) / 128, 128>>>(p_agg, W3, aS3, aD3, N);
    k_attn3<<<attnBlocks, 256>>>(b3, out, N);
}

// round 14
// speedup vs baseline: 1.0015x; 1.0015x over previous
#include <cuda_runtime.h>

#define NMAX 100000
#define EMAX 1600000
#define TOTEMAX (NMAX + EMAX)

// ---------------- scratch (static device globals; no allocation) ----------------
__device__ float g_hfeat[(size_t)NMAX * 128];          // per-layer linear features
__device__ float g_agg[(size_t)NMAX * 128];            // aggregated output (post-ELU)
__device__ float g_alpha[(size_t)TOTEMAX * 8];         // per-edge exp(e - m) per head
__device__ float g_as[(size_t)NMAX * 8];
__device__ float g_ad[(size_t)NMAX * 8];
__device__ float g_feat3[(size_t)NMAX * 6];
__device__ float g_as3[NMAX];
__device__ float g_ad3[NMAX];
__device__ int   g_cnt[NMAX];
__device__ int   g_rowstart[NMAX + 1];
__device__ int   g_fill[NMAX];
__device__ int   g_adj[TOTEMAX];
__device__ int   g_bsum[256];
__device__ int   g_boff[256];

// ---------------- CSR build ----------------
__global__ void k_count_init(int n) {
    int i = blockIdx.x * blockDim.x + threadIdx.x;
    if (i < n) g_cnt[i] = 1;  // self-loop
}

// edge_index is int32 (JAX x64 is disabled; jnp.int64 silently demotes to int32)
__global__ void k_count_edges(const int* __restrict__ ei, int E, int n) {
    int e = blockIdx.x * blockDim.x + threadIdx.x;
    if (e < E) {
        int d = ei[(size_t)E + e];
        if (d >= 0 && d < n) atomicAdd(&g_cnt[d], 1);
    }
}

// block of 256 threads scans 1024 items
__global__ void k_scan_local(int n) {
    __shared__ int sh[256];
    int t = threadIdx.x;
    int base = blockIdx.x * 1024 + t * 4;
    int v0 = (base + 0 < n) ? g_cnt[base + 0] : 0;
    int v1 = (base + 1 < n) ? g_cnt[base + 1] : 0;
    int v2 = (base + 2 < n) ? g_cnt[base + 2] : 0;
    int v3 = (base + 3 < n) ? g_cnt[base + 3] : 0;
    int s = v0 + v1 + v2 + v3;
    sh[t] = s;
    __syncthreads();
    for (int o = 1; o < 256; o <<= 1) {
        int x = (t >= o) ? sh[t - o] : 0;
        __syncthreads();
        sh[t] += x;
        __syncthreads();
    }
    int run = sh[t] - s;  // exclusive prefix of this thread within block
    if (base + 0 < n) g_rowstart[base + 0] = run; run += v0;
    if (base + 1 < n) g_rowstart[base + 1] = run; run += v1;
    if (base + 2 < n) g_rowstart[base + 2] = run; run += v2;
    if (base + 3 < n) g_rowstart[base + 3] = run;
    if (t == 255) g_bsum[blockIdx.x] = sh[255];
}

__global__ void k_scan_tops(int nb) {
    if (threadIdx.x == 0 && blockIdx.x == 0) {
        int run = 0;
        for (int b = 0; b < nb; b++) { g_boff[b] = run; run += g_bsum[b]; }
    }
}

__global__ void k_scan_apply(int n) {
    int i = blockIdx.x * blockDim.x + threadIdx.x;
    if (i < n) {
        int rs = g_rowstart[i] + g_boff[i >> 10];
        g_rowstart[i] = rs;
        g_fill[i] = rs;
        if (i == n - 1) g_rowstart[n] = rs + g_cnt[i];
    }
}

__global__ void k_fill(const int* __restrict__ ei, int E, int n) {
    int idx = blockIdx.x * blockDim.x + threadIdx.x;
    if (idx < E) {
        int s = ei[idx];
        int d = ei[(size_t)E + idx];
        if (d >= 0 && d < n && s >= 0 && s < n) {
            int pos = atomicAdd(&g_fill[d], 1);
            if (pos >= 0 && pos < TOTEMAX) g_adj[pos] = s;
        }
    } else if (idx < E + n) {
        int v = idx - E;
        int pos = atomicAdd(&g_fill[v], 1);
        if (pos >= 0 && pos < TOTEMAX) g_adj[pos] = v;
    }
}

// ---------------- SGEMM: C[nrows,K] = A[nrows,M] @ B[M,K]  (128x128 tile, 8x8/thread) ----------------
__global__ __launch_bounds__(256) void k_gemm(const float* __restrict__ A,
                                              const float* __restrict__ B,
                                              float* __restrict__ C,
                                              int nrows, int M, int K) {
    __shared__ float As[8][128];
    __shared__ float Bs[8][128];
    int tid = threadIdx.x;
    int rowBase = blockIdx.x * 128;
    int colBase = blockIdx.y * 128;
    int aRow = tid >> 1;
    int aCol = (tid & 1) * 4;
    int bRow = tid >> 5;
    int bCol = (tid & 31) * 4;
    int ty = tid >> 4, tx = tid & 15;

    float acc[8][8];
#pragma unroll
    for (int i = 0; i < 8; i++)
#pragma unroll
        for (int j = 0; j < 8; j++) acc[i][j] = 0.0f;

    for (int k0 = 0; k0 < M; k0 += 8) {
        float4 av = make_float4(0.f, 0.f, 0.f, 0.f);
        int r = rowBase + aRow;
        if (r < nrows) av = *reinterpret_cast<const float4*>(A + (size_t)r * M + k0 + aCol);
        As[aCol + 0][aRow] = av.x;
        As[aCol + 1][aRow] = av.y;
        As[aCol + 2][aRow] = av.z;
        As[aCol + 3][aRow] = av.w;
        float4 bv = *reinterpret_cast<const float4*>(B + (size_t)(k0 + bRow) * K + colBase + bCol);
        *reinterpret_cast<float4*>(&Bs[bRow][bCol]) = bv;
        __syncthreads();
#pragma unroll
        for (int kk = 0; kk < 8; kk++) {
            float ar[8], br[8];
#pragma unroll
            for (int i = 0; i < 8; i++) ar[i] = As[kk][ty * 8 + i];
#pragma unroll
            for (int j = 0; j < 8; j++) br[j] = Bs[kk][tx * 8 + j];
#pragma unroll
            for (int i = 0; i < 8; i++)
#pragma unroll
                for (int j = 0; j < 8; j++) acc[i][j] += ar[i] * br[j];
        }
        __syncthreads();
    }
#pragma unroll
    for (int i = 0; i < 8; i++) {
        int r = rowBase + ty * 8 + i;
        if (r < nrows) {
            float4 v0 = make_float4(acc[i][0], acc[i][1], acc[i][2], acc[i][3]);
            float4 v1 = make_float4(acc[i][4], acc[i][5], acc[i][6], acc[i][7]);
            *reinterpret_cast<float4*>(C + (size_t)r * K + colBase + tx * 8) = v0;
            *reinterpret_cast<float4*>(C + (size_t)r * K + colBase + tx * 8 + 4) = v1;
        }
    }
}

// ---------------- attention coefficients a_s, a_d  (8 heads x 16 dims) ----------------
__global__ void k_coef(const float* __restrict__ h, const float* __restrict__ attS,
                       const float* __restrict__ attD, int n) {
    int idx = blockIdx.x * blockDim.x + threadIdx.x;
    if (idx >= n * 8) return;
    int node = idx >> 3, hh = idx & 7;
    const float* hp = h + (size_t)node * 128 + hh * 16;
    const float* sp = attS + hh * 16;
    const float* dp = attD + hh * 16;
    float a = 0.f, b = 0.f;
#pragma unroll
    for (int j = 0; j < 16; j++) {
        float v = hp[j];
        a += v * sp[j];
        b += v * dp[j];
    }
    g_as[idx] = a;
    g_ad[idx] = b;
}

// ---------------- per-node softmax + aggregation (layers 1/2, H=8, D=16) ----------------
__global__ __launch_bounds__(256) void k_attn(const float* __restrict__ hfeat,
                                              float* __restrict__ outbuf,
                                              const float* __restrict__ bias,
                                              int n, int applyElu) {
    int w = (int)((blockIdx.x * blockDim.x + threadIdx.x) >> 5);
    int lane = threadIdx.x & 31;
    if (w >= n) return;
    int r0 = g_rowstart[w];
    int r1 = g_rowstart[w + 1];

    float ad[8];
    {
        const float4* adp = reinterpret_cast<const float4*>(g_ad + (size_t)w * 8);
        float4 d0 = adp[0], d1 = adp[1];
        ad[0] = d0.x; ad[1] = d0.y; ad[2] = d0.z; ad[3] = d0.w;
        ad[4] = d1.x; ad[5] = d1.y; ad[6] = d1.z; ad[7] = d1.w;
    }

    // pass 1: per-head max
    float mx[8];
#pragma unroll
    for (int h = 0; h < 8; h++) mx[h] = -3.4e38f;
    for (int i = r0 + lane; i < r1; i += 32) {
        int s = g_adj[i];
        const float4* ap = reinterpret_cast<const float4*>(g_as + (size_t)s * 8);
        float4 A0 = ap[0], A1 = ap[1];
        float ev[8] = {A0.x + ad[0], A0.y + ad[1], A0.z + ad[2], A0.w + ad[3],
                       A1.x + ad[4], A1.y + ad[5], A1.z + ad[6], A1.w + ad[7]};
#pragma unroll
        for (int h = 0; h < 8; h++) {
            float e = ev[h];
            e = (e > 0.f) ? e : 0.2f * e;
            mx[h] = fmaxf(mx[h], e);
        }
    }
#pragma unroll
    for (int h = 0; h < 8; h++)
        for (int o = 16; o > 0; o >>= 1)
            mx[h] = fmaxf(mx[h], __shfl_xor_sync(0xffffffffu, mx[h], o));

    // pass 2: exp(e - m), store, accumulate denominator
    float den[8];
#pragma unroll
    for (int h = 0; h < 8; h++) den[h] = 0.f;
    for (int i = r0 + lane; i < r1; i += 32) {
        int s = g_adj[i];
        const float4* ap = reinterpret_cast<const float4*>(g_as + (size_t)s * 8);
        float4 A0 = ap[0], A1 = ap[1];
        float ev[8] = {A0.x + ad[0], A0.y + ad[1], A0.z + ad[2], A0.w + ad[3],
                       A1.x + ad[4], A1.y + ad[5], A1.z + ad[6], A1.w + ad[7]};
        float ex[8];
#pragma unroll
        for (int h = 0; h < 8; h++) {
            float e = ev[h];
            e = (e > 0.f) ? e : 0.2f * e;
            float xx = __expf(e - mx[h]);
            ex[h] = xx;
            den[h] += xx;
        }
        float4* alp = reinterpret_cast<float4*>(g_alpha + (size_t)i * 8);
        alp[0] = make_float4(ex[0], ex[1], ex[2], ex[3]);
        alp[1] = make_float4(ex[4], ex[5], ex[6], ex[7]);
    }
    float inv[8];
#pragma unroll
    for (int h = 0; h < 8; h++) {
        for (int o = 16; o > 0; o >>= 1)
            den[h] += __shfl_xor_sync(0xffffffffu, den[h], o);
        inv[h] = 1.0f / (den[h] + 1e-16f);
    }

    // pass 3: feature aggregation. lane owns columns [lane*4, lane*4+4), head = lane/4
    int cb = lane * 4;
    int hh = lane >> 2;
    float invm = inv[0];
#pragma unroll
    for (int h = 1; h < 8; h++)
        if (hh == h) invm = inv[h];

    float4 acc = make_float4(0.f, 0.f, 0.f, 0.f);
    for (int i = r0; i < r1; i++) {
        int s = g_adj[i];
        float al = g_alpha[(size_t)i * 8 + hh] * invm;
        float4 hv = *reinterpret_cast<const float4*>(hfeat + (size_t)s * 128 + cb);
        acc.x += hv.x * al;
        acc.y += hv.y * al;
        acc.z += hv.z * al;
        acc.w += hv.w * al;
    }
    float4 bo = *reinterpret_cast<const float4*>(bias + cb);
    acc.x += bo.x; acc.y += bo.y; acc.z += bo.z; acc.w += bo.w;
    if (applyElu) {
        acc.x = (acc.x > 0.f) ? acc.x : (__expf(acc.x) - 1.f);
        acc.y = (acc.y > 0.f) ? acc.y : (__expf(acc.y) - 1.f);
        acc.z = (acc.z > 0.f) ? acc.z : (__expf(acc.z) - 1.f);
        acc.w = (acc.w > 0.f) ? acc.w : (__expf(acc.w) - 1.f);
    }
    *reinterpret_cast<float4*>(outbuf + (size_t)w * 128 + cb) = acc;
}

// ---------------- layer 3: tiny GEMM (128->6) + attention coefficients fused ----------------
__global__ void k_layer3(const float* __restrict__ h, const float* __restrict__ W3,
                         const float* __restrict__ aS, const float* __restrict__ aD, int n) {
    int v = blockIdx.x * blockDim.x + threadIdx.x;
    if (v >= n) return;
    float acc[6] = {0.f, 0.f, 0.f, 0.f, 0.f, 0.f};
    const float* hp = h + (size_t)v * 128;
    for (int m = 0; m < 128; m++) {
        float hv = hp[m];
#pragma unroll
        for (int c = 0; c < 6; c++) acc[c] += hv * W3[m * 6 + c];
    }
    float a = 0.f, b = 0.f;
#pragma unroll
    for (int c = 0; c < 6; c++) {
        g_feat3[(size_t)v * 6 + c] = acc[c];
        a += acc[c] * aS[c];
        b += acc[c] * aD[c];
    }
    g_as3[v] = a;
    g_ad3[v] = b;
}

// ---------------- layer 3 attention (H=1, C=6) -> final output ----------------
__global__ __launch_bounds__(256) void k_attn3(const float* __restrict__ b3,
                                               float* __restrict__ out, int n) {
    int w = (int)((blockIdx.x * blockDim.x + threadIdx.x) >> 5);
    int lane = threadIdx.x & 31;
    if (w >= n) return;
    int r0 = g_rowstart[w];
    int r1 = g_rowstart[w + 1];
    float adv = g_ad3[w];

    float mx = -3.4e38f;
    for (int i = r0 + lane; i < r1; i += 32) {
        int s = g_adj[i];
        float e = g_as3[s] + adv;
        e = (e > 0.f) ? e : 0.2f * e;
        mx = fmaxf(mx, e);
    }
    for (int o = 16; o > 0; o >>= 1)
        mx = fmaxf(mx, __shfl_xor_sync(0xffffffffu, mx, o));

    float den = 0.f;
    for (int i = r0 + lane; i < r1; i += 32) {
        int s = g_adj[i];
        float e = g_as3[s] + adv;
        e = (e > 0.f) ? e : 0.2f * e;
        den += __expf(e - mx);
    }
    for (int o = 16; o > 0; o >>= 1)
        den += __shfl_xor_sync(0xffffffffu, den, o);
    float inv = 1.0f / (den + 1e-16f);

    float acc[6] = {0.f, 0.f, 0.f, 0.f, 0.f, 0.f};
    for (int i = r0 + lane; i < r1; i += 32) {
        int s = g_adj[i];
        float e = g_as3[s] + adv;
        e = (e > 0.f) ? e : 0.2f * e;
        float al = __expf(e - mx) * inv;
#pragma unroll
        for (int c = 0; c < 6; c++) acc[c] += g_feat3[(size_t)s * 6 + c] * al;
    }
#pragma unroll
    for (int c = 0; c < 6; c++)
        for (int o = 16; o > 0; o >>= 1)
            acc[c] += __shfl_xor_sync(0xffffffffu, acc[c], o);

    if (lane < 6) {
        float v = acc[0];
#pragma unroll
        for (int c = 1; c < 6; c++)
            if (lane == c) v = acc[c];
        out[(size_t)w * 6 + lane] = v + b3[lane];
    }
}

// ---------------- launch ----------------
extern "C" void kernel_launch(void* const* d_in, const int* in_sizes, int n_in,
                              void* d_out, int out_size) {
    const float* x    = (const float*)d_in[0];
    const int*   ei   = (const int*)d_in[1];   // int32! (JAX x64 disabled demotes int64)
    const float* W1   = (const float*)d_in[2];
    const float* b1   = (const float*)d_in[3];
    const float* aS1  = (const float*)d_in[4];
    const float* aD1  = (const float*)d_in[5];
    const float* W2   = (const float*)d_in[6];
    const float* b2   = (const float*)d_in[7];
    const float* aS2  = (const float*)d_in[8];
    const float* aD2  = (const float*)d_in[9];
    const float* W3   = (const float*)d_in[10];
    const float* b3   = (const float*)d_in[11];
    const float* aS3  = (const float*)d_in[12];
    const float* aD3  = (const float*)d_in[13];
    float* out = (float*)d_out;

    int N = in_sizes[0] / 256;
    int E = in_sizes[1] / 2;
    int TE = E + N;

    float *p_hfeat, *p_agg;
    cudaGetSymbolAddress((void**)&p_hfeat, g_hfeat);
    cudaGetSymbolAddress((void**)&p_agg, g_agg);

    // ---- CSR build (by destination) ----
    k_count_init<<<(N + 255) / 256, 256>>>(N);
    k_count_edges<<<(E + 255) / 256, 256>>>(ei, E, N);
    int nb = (N + 1023) / 1024;
    k_scan_local<<<nb, 256>>>(N);
    k_scan_tops<<<1, 32>>>(nb);
    k_scan_apply<<<(N + 255) / 256, 256>>>(N);
    k_fill<<<(TE + 255) / 256, 256>>>(ei, E, N);

    dim3 ggrid((N + 127) / 128, 1);
    int attnBlocks = (N + 7) / 8;

    // ---- layer 1 ----
    k_gemm<<<ggrid, 256>>>(x, W1, p_hfeat, N, 256, 128);
    k_coef<<<(N * 8 + 255) / 256, 256>>>(p_hfeat, aS1, aD1, N);
    k_attn<<<attnBlocks, 256>>>(p_hfeat, p_agg, b1, N, 1);

    // ---- layer 2 ----
    k_gemm<<<ggrid, 256>>>(p_agg, W2, p_hfeat, N, 128, 128);
    k_coef<<<(N * 8 + 255) / 256, 256>>>(p_hfeat, aS2, aD2, N);
    k_attn<<<attnBlocks, 256>>>(p_hfeat, p_agg, b2, N, 1);

    // ---- layer 3 ----
    k_layer3<<<(N + 127) / 128, 128>>>(p_agg, W3, aS3, aD3, N);
    k_attn3<<<attnBlocks, 256>>>(b3, out, N);
}